// round 2
// baseline (speedup 1.0000x reference)
#include <cuda_runtime.h>
#include <cuda_bf16.h>
#include <math.h>

// Problem constants
#define B   128
#define L   512
#define FIN 128
#define FOUT 128
#define ALPHA 0.2f

// Scratch (device globals — no allocation allowed)
__device__ float g_Wh[(size_t)B * L * FOUT];   // 33.5 MB
__device__ float g_ei[B * L];
__device__ float g_ej[B * L];
__device__ int   g_maskKind;   // 0=int32, 1=uint8, 2=float32

// ---------------------------------------------------------------------------
// Kernel 0: detect adj_mask storage layout. The mask buffer is a bool array
// whose on-device dtype is unknown (int32 / packed bytes / float32). Probe
// the first 65536 32-bit words (safe under all three layouts: the smallest,
// uint8, is exactly 256KB = 65536 words).
//   word == 0x3F800000           -> float32 1.0f (ints/bytes 0/1 never hit it)
//   word > 1 (and not that)      -> packed uint8 bools
//   else                         -> int32 0/1
// ---------------------------------------------------------------------------
__global__ void k_detect(const unsigned int* __restrict__ m) {
    __shared__ int sgt1, sflt;
    if (threadIdx.x == 0) { sgt1 = 0; sflt = 0; }
    __syncthreads();
    int gt1 = 0, flt = 0;
    for (int i = threadIdx.x; i < 65536; i += blockDim.x) {
        unsigned w = m[i];
        if (w == 0x3F800000u) flt = 1;
        else if (w > 1u)      gt1 = 1;
    }
    if (gt1) atomicOr(&sgt1, 1);
    if (flt) atomicOr(&sflt, 1);
    __syncthreads();
    if (threadIdx.x == 0)
        g_maskKind = sflt ? 2 : (sgt1 ? 1 : 0);
}

// ---------------------------------------------------------------------------
// Kernel 1: Wh = h @ W   (M = B*L = 65536, K = 128, N = 128), fp32 tiled
// ---------------------------------------------------------------------------
__global__ __launch_bounds__(256) void k_gemm1(const float* __restrict__ h,
                                               const float* __restrict__ W) {
    __shared__ float hs[64][32];
    __shared__ float Ws[32][128];

    const int t  = threadIdx.x;
    const int ty = t >> 4;
    const int tx = t & 15;

    const long rowBase = (long)blockIdx.x * 64;
    float acc[4][8];
    #pragma unroll
    for (int r = 0; r < 4; r++)
        #pragma unroll
        for (int c = 0; c < 8; c++) acc[r][c] = 0.f;

    for (int kc = 0; kc < FIN; kc += 32) {
        __syncthreads();
        for (int l = t; l < 512; l += 256) {
            int r = l >> 3, c4 = l & 7;
            *(float4*)&hs[r][c4 * 4] =
                *(const float4*)(h + (rowBase + r) * FIN + kc + c4 * 4);
        }
        for (int l = t; l < 1024; l += 256) {
            int r = l >> 5, c4 = l & 31;
            *(float4*)&Ws[r][c4 * 4] =
                *(const float4*)(W + (kc + r) * FOUT + c4 * 4);
        }
        __syncthreads();

        #pragma unroll
        for (int k = 0; k < 32; k++) {
            float av[4];
            #pragma unroll
            for (int r = 0; r < 4; r++) av[r] = hs[ty * 4 + r][k];
            float4 w0 = *(float4*)&Ws[k][tx * 8];
            float4 w1 = *(float4*)&Ws[k][tx * 8 + 4];
            float bv[8] = {w0.x, w0.y, w0.z, w0.w, w1.x, w1.y, w1.z, w1.w};
            #pragma unroll
            for (int r = 0; r < 4; r++)
                #pragma unroll
                for (int c = 0; c < 8; c++)
                    acc[r][c] = fmaf(av[r], bv[c], acc[r][c]);
        }
    }

    #pragma unroll
    for (int r = 0; r < 4; r++) {
        float* o = g_Wh + (rowBase + ty * 4 + r) * FOUT + tx * 8;
        float4 v0 = {acc[r][0], acc[r][1], acc[r][2], acc[r][3]};
        float4 v1 = {acc[r][4], acc[r][5], acc[r][6], acc[r][7]};
        *(float4*)o       = v0;
        *(float4*)(o + 4) = v1;
    }
}

// ---------------------------------------------------------------------------
// Kernel 1b: ei = Wh @ a[:F], ej = Wh @ a[F:]  (one warp per row)
// ---------------------------------------------------------------------------
__global__ __launch_bounds__(256) void k_eiej(const float* __restrict__ a) {
    const int warp = (blockIdx.x * blockDim.x + threadIdx.x) >> 5;
    const int lane = threadIdx.x & 31;
    if (warp >= B * L) return;
    const float* row = g_Wh + (long)warp * FOUT;
    float s1 = 0.f, s2 = 0.f;
    #pragma unroll
    for (int k = lane; k < FOUT; k += 32) {
        float v = row[k];
        s1 = fmaf(v, a[k], s1);
        s2 = fmaf(v, a[FOUT + k], s2);
    }
    #pragma unroll
    for (int o = 16; o; o >>= 1) {
        s1 += __shfl_xor_sync(0xFFFFFFFFu, s1, o);
        s2 += __shfl_xor_sync(0xFFFFFFFFu, s2, o);
    }
    if (lane == 0) { g_ei[warp] = s1; g_ej[warp] = s2; }
}

// ---------------------------------------------------------------------------
// Kernel 2: fused attention (no online softmax needed: logits are O(+-6),
// fp32 exp is safe; masked -> p = 0 exactly). Unnormalized accumulation,
// divide + ELU in epilogue.
// ---------------------------------------------------------------------------
#define PS_LD 68  // padded row stride for p tile

__global__ __launch_bounds__(256) void k_attn(const float* __restrict__ bias,
                                              const void* __restrict__ adj,
                                              float* __restrict__ out) {
    extern __shared__ float sm[];
    float* Whs = sm;                  // 64 * 128
    float* ps  = sm + 64 * 128;       // 64 * PS_LD
    float* eis = ps + 64 * PS_LD;     // 64

    const int kind = g_maskKind;
    const int* adjI = (const int*)adj;
    const unsigned char* adjB = (const unsigned char*)adj;
    const float* adjF = (const float*)adj;

    const int b  = blockIdx.y;
    const int i0 = blockIdx.x * 64;
    const int t  = threadIdx.x;
    const int ty = t >> 4;            // rows ty*4..+3
    const int tx = t & 15;            // cols tx*8..+7

    if (t < 64) eis[t] = g_ei[b * L + i0 + t];

    const float* Whb = g_Wh + (long)b * L * FOUT;
    const float* ejb = g_ej + b * L;

    float acc[4][8];
    #pragma unroll
    for (int r = 0; r < 4; r++)
        #pragma unroll
        for (int c = 0; c < 8; c++) acc[r][c] = 0.f;
    float sreg[4] = {0.f, 0.f, 0.f, 0.f};

    const int jj     = t & 63;
    const int iiBase = (t >> 6) * 16;

    for (int jt = 0; jt < 8; jt++) {
        const int j0 = jt * 64;
        __syncthreads();  // previous-iteration GEMM reads complete

        // load Wh tile: 64 rows x 128 cols = 2048 float4
        for (int l = t; l < 2048; l += 256)
            *(float4*)&Whs[l * 4] = *(const float4*)(Whb + j0 * FOUT + l * 4);

        // compute p tile
        {
            const float ejv = ejb[j0 + jj];
            const long base = (long)(i0 + iiBase) * L + j0 + jj;
            const float* bRow = bias + (long)b * L * L + base;
            #pragma unroll
            for (int q = 0; q < 16; q++) {
                const int ii = iiBase + q;
                float x = eis[ii] + ejv;
                x = x > 0.f ? x : ALPHA * x;
                x += bRow[(long)q * L];
                const long mIdx = base + (long)q * L;
                bool m;
                if (kind == 0)      m = adjI[mIdx] != 0;
                else if (kind == 1) m = adjB[mIdx] != 0;
                else                m = adjF[mIdx] != 0.f;
                ps[ii * PS_LD + jj] = m ? __expf(x) : 0.f;
            }
        }
        __syncthreads();

        // micro-GEMM: acc[64x128] += p[64x64] @ Wh[64x128]
        #pragma unroll 4
        for (int j = 0; j < 64; j++) {
            float pr[4];
            #pragma unroll
            for (int r = 0; r < 4; r++) pr[r] = ps[(ty * 4 + r) * PS_LD + j];
            float4 w0 = *(float4*)&Whs[j * FOUT + tx * 8];
            float4 w1 = *(float4*)&Whs[j * FOUT + tx * 8 + 4];
            float bv[8] = {w0.x, w0.y, w0.z, w0.w, w1.x, w1.y, w1.z, w1.w};
            #pragma unroll
            for (int r = 0; r < 4; r++) {
                sreg[r] += pr[r];
                #pragma unroll
                for (int c = 0; c < 8; c++)
                    acc[r][c] = fmaf(pr[r], bv[c], acc[r][c]);
            }
        }
    }

    #pragma unroll
    for (int r = 0; r < 4; r++) {
        const float inv = 1.f / sreg[r];
        float* o = out + ((long)b * L + i0 + ty * 4 + r) * FOUT + tx * 8;
        float v[8];
        #pragma unroll
        for (int c = 0; c < 8; c++) {
            float x = acc[r][c] * inv;
            v[c] = x > 0.f ? x : expm1f(x);
        }
        float4 v0 = {v[0], v[1], v[2], v[3]};
        float4 v1 = {v[4], v[5], v[6], v[7]};
        *(float4*)o       = v0;
        *(float4*)(o + 4) = v1;
    }
}

// ---------------------------------------------------------------------------
extern "C" void kernel_launch(void* const* d_in, const int* in_sizes, int n_in,
                              void* d_out, int out_size) {
    const float* h    = (const float*)d_in[0];
    const float* W    = (const float*)d_in[1];
    const float* a    = (const float*)d_in[2];
    const float* bias = (const float*)d_in[3];
    const void*  adj  = d_in[4];
    float* out = (float*)d_out;

    k_detect<<<1, 256>>>((const unsigned int*)adj);
    k_gemm1<<<(B * L) / 64, 256>>>(h, W);
    k_eiej<<<(B * L) / 8, 256>>>(a);

    const int smem = (64 * 128 + 64 * PS_LD + 64) * (int)sizeof(float);
    cudaFuncSetAttribute(k_attn, cudaFuncAttributeMaxDynamicSharedMemorySize, smem);
    dim3 grid(L / 64, B);
    k_attn<<<grid, 256, smem>>>(bias, adj, out);
}

// round 3
// speedup vs baseline: 1.2170x; 1.2170x over previous
#include <cuda_runtime.h>
#include <cuda_bf16.h>
#include <math.h>

#define B    128
#define L    512
#define FIN  128
#define FOUT 128
#define ALPHA 0.2f

// Scratch (device globals — no allocation allowed)
__device__ float g_Wh[(size_t)B * L * FOUT];   // 33.5 MB
__device__ float g_ei[B * L];
__device__ float g_ej[B * L];
__device__ int   g_maskKind;   // 0=int32, 1=uint8, 2=float32

// ---------------------------------------------------------------------------
// Kernel 0: detect adj_mask storage layout (bool dtype on device is unknown).
//   word == 0x3F800000 -> float32 1.0f ; word > 1 -> packed uint8 ; else int32
// ---------------------------------------------------------------------------
__global__ void k_detect(const unsigned int* __restrict__ m) {
    __shared__ int sgt1, sflt;
    if (threadIdx.x == 0) { sgt1 = 0; sflt = 0; }
    __syncthreads();
    int gt1 = 0, flt = 0;
    for (int i = threadIdx.x; i < 65536; i += blockDim.x) {
        unsigned w = m[i];
        if (w == 0x3F800000u) flt = 1;
        else if (w > 1u)      gt1 = 1;
    }
    if (gt1) atomicOr(&sgt1, 1);
    if (flt) atomicOr(&sflt, 1);
    __syncthreads();
    if (threadIdx.x == 0)
        g_maskKind = sflt ? 2 : (sgt1 ? 1 : 0);
}

// ---------------------------------------------------------------------------
// Kernel 1: Wh = h @ W  (M=65536, K=128, N=128) 128x128 tile, 8x8 micro-tile,
// fused epilogue: ei = Wh@a[:F], ej = Wh@a[F:]  (shuffle-reduced per row).
// ---------------------------------------------------------------------------
#define HT_LD 132

__global__ __launch_bounds__(256, 2) void k_gemm1(const float* __restrict__ h,
                                                  const float* __restrict__ W,
                                                  const float* __restrict__ a) {
    __shared__ float hsT[32][HT_LD];   // transposed h tile: [k][i]
    __shared__ float Ws[32][128];      // [k][n]

    const int t  = threadIdx.x;
    const int tr = t >> 4;             // 0..15 -> rows tr*8..+7
    const int tc = t & 15;             // 0..15 -> cols tc*8..+7

    const long rowBase = (long)blockIdx.x * 128;

    float acc[8][8];
    #pragma unroll
    for (int r = 0; r < 8; r++)
        #pragma unroll
        for (int c = 0; c < 8; c++) acc[r][c] = 0.f;

    for (int kc = 0; kc < FIN; kc += 32) {
        __syncthreads();
        // h tile: 128 rows x 32 k = 1024 float4, scattered transposed
        for (int l = t; l < 1024; l += 256) {
            int i = l >> 3, k4 = l & 7;
            float4 v = *(const float4*)(h + (rowBase + i) * FIN + kc + k4 * 4);
            hsT[k4 * 4 + 0][i] = v.x;
            hsT[k4 * 4 + 1][i] = v.y;
            hsT[k4 * 4 + 2][i] = v.z;
            hsT[k4 * 4 + 3][i] = v.w;
        }
        // W tile: 32 x 128 = 1024 float4
        for (int l = t; l < 1024; l += 256) {
            int r = l >> 5, c4 = l & 31;
            *(float4*)&Ws[r][c4 * 4] =
                *(const float4*)(W + (kc + r) * FOUT + c4 * 4);
        }
        __syncthreads();

        #pragma unroll
        for (int k = 0; k < 32; k++) {
            float4 a0 = *(float4*)&hsT[k][tr * 8];
            float4 a1 = *(float4*)&hsT[k][tr * 8 + 4];
            float4 b0 = *(float4*)&Ws[k][tc * 8];
            float4 b1 = *(float4*)&Ws[k][tc * 8 + 4];
            float av[8] = {a0.x, a0.y, a0.z, a0.w, a1.x, a1.y, a1.z, a1.w};
            float bv[8] = {b0.x, b0.y, b0.z, b0.w, b1.x, b1.y, b1.z, b1.w};
            #pragma unroll
            for (int r = 0; r < 8; r++)
                #pragma unroll
                for (int c = 0; c < 8; c++)
                    acc[r][c] = fmaf(av[r], bv[c], acc[r][c]);
        }
    }

    // store Wh
    #pragma unroll
    for (int r = 0; r < 8; r++) {
        float* o = g_Wh + (rowBase + tr * 8 + r) * FOUT + tc * 8;
        float4 v0 = {acc[r][0], acc[r][1], acc[r][2], acc[r][3]};
        float4 v1 = {acc[r][4], acc[r][5], acc[r][6], acc[r][7]};
        *(float4*)o       = v0;
        *(float4*)(o + 4) = v1;
    }

    // fused ei/ej: per-row dot with attention vector, reduce over 16 tc lanes
    float av1[8], av2[8];
    #pragma unroll
    for (int c = 0; c < 8; c++) {
        av1[c] = a[tc * 8 + c];
        av2[c] = a[FOUT + tc * 8 + c];
    }
    #pragma unroll
    for (int r = 0; r < 8; r++) {
        float s1 = 0.f, s2 = 0.f;
        #pragma unroll
        for (int c = 0; c < 8; c++) {
            s1 = fmaf(acc[r][c], av1[c], s1);
            s2 = fmaf(acc[r][c], av2[c], s2);
        }
        #pragma unroll
        for (int o = 8; o; o >>= 1) {
            s1 += __shfl_xor_sync(0xFFFFFFFFu, s1, o);
            s2 += __shfl_xor_sync(0xFFFFFFFFu, s2, o);
        }
        if (tc == 0) {
            g_ei[rowBase + tr * 8 + r] = s1;
            g_ej[rowBase + tr * 8 + r] = s2;
        }
    }
}

// ---------------------------------------------------------------------------
// Kernel 2: fused attention. Block = (128 i-rows, batch b), streams 8 j-tiles
// of 64. p stored TRANSPOSED in smem so the GEMM A-operand is float4.
// No online softmax needed (logits O(+-6)); unnormalized accumulation,
// divide + ELU in epilogue.
// ---------------------------------------------------------------------------
#define PT_LD 132   // psT row stride (floats), 16B-aligned, conflict-benign

__global__ __launch_bounds__(256, 2) void k_attn(const float* __restrict__ bias,
                                                 const void* __restrict__ adj,
                                                 float* __restrict__ out) {
    extern __shared__ float sm[];
    float* Whs = sm;                       // [64][128]
    float* psT = sm + 64 * 128;            // [64][PT_LD]  p transposed: [j][i]
    float* eis = psT + 64 * PT_LD;         // [128]

    const int kind = g_maskKind;
    const int* adjI = (const int*)adj;
    const unsigned char* adjB = (const unsigned char*)adj;
    const float* adjF = (const float*)adj;

    const int b  = blockIdx.y;
    const int i0 = blockIdx.x * 128;
    const int t  = threadIdx.x;
    const int tr = t >> 4;                 // rows tr*8..+7  (16 groups x 8 = 128)
    const int tc = t & 15;                 // cols tc*8..+7  (16 groups x 8 = 128)

    if (t < 128) eis[t] = g_ei[b * L + i0 + t];

    const float* Whb = g_Wh + (long)b * L * FOUT;
    const float* ejb = g_ej + b * L;

    float acc[8][8];
    #pragma unroll
    for (int r = 0; r < 8; r++)
        #pragma unroll
        for (int c = 0; c < 8; c++) acc[r][c] = 0.f;
    float sreg[8] = {0.f, 0.f, 0.f, 0.f, 0.f, 0.f, 0.f, 0.f};

    // p-tile mapping: jj = t & 63 (64 j), row group = t >> 6 (4 x 32 rows)
    const int jj     = t & 63;
    const int iiBase = (t >> 6) * 32;

    for (int jt = 0; jt < 8; jt++) {
        const int j0 = jt * 64;
        __syncthreads();   // previous-iteration smem reads complete

        // Wh tile: 64 rows x 128 cols = 2048 float4
        for (int l = t; l < 2048; l += 256)
            *(float4*)&Whs[l * 4] = *(const float4*)(Whb + j0 * FOUT + l * 4);

        // p tile (transposed store)
        {
            const float ejv = ejb[j0 + jj];
            const long base = (long)(i0 + iiBase) * L + j0 + jj;
            const float* bRow = bias + (long)b * L * L + base;
            #pragma unroll 8
            for (int q = 0; q < 32; q++) {
                const int ii = iiBase + q;
                float x = eis[ii] + ejv;
                x = x > 0.f ? x : ALPHA * x;
                x += bRow[(long)q * L];
                const long mIdx = base + (long)q * L;
                bool m;
                if (kind == 0)      m = adjI[mIdx] != 0;
                else if (kind == 1) m = adjB[mIdx] != 0;
                else                m = adjF[mIdx] != 0.f;
                psT[jj * PT_LD + ii] = m ? __expf(x) : 0.f;
            }
        }
        __syncthreads();

        // micro-GEMM: acc[128x128] += p[128x64] @ Wh[64x128]
        #pragma unroll 8
        for (int j = 0; j < 64; j++) {
            float4 a0 = *(float4*)&psT[j * PT_LD + tr * 8];
            float4 a1 = *(float4*)&psT[j * PT_LD + tr * 8 + 4];
            float4 b0 = *(float4*)&Whs[j * FOUT + tc * 8];
            float4 b1 = *(float4*)&Whs[j * FOUT + tc * 8 + 4];
            float av[8] = {a0.x, a0.y, a0.z, a0.w, a1.x, a1.y, a1.z, a1.w};
            float bv[8] = {b0.x, b0.y, b0.z, b0.w, b1.x, b1.y, b1.z, b1.w};
            #pragma unroll
            for (int r = 0; r < 8; r++) {
                sreg[r] += av[r];
                #pragma unroll
                for (int c = 0; c < 8; c++)
                    acc[r][c] = fmaf(av[r], bv[c], acc[r][c]);
            }
        }
    }

    #pragma unroll
    for (int r = 0; r < 8; r++) {
        const float inv = 1.f / sreg[r];
        float* o = out + ((long)b * L + i0 + tr * 8 + r) * FOUT + tc * 8;
        float v[8];
        #pragma unroll
        for (int c = 0; c < 8; c++) {
            float x = acc[r][c] * inv;
            v[c] = x > 0.f ? x : expm1f(x);
        }
        float4 v0 = {v[0], v[1], v[2], v[3]};
        float4 v1 = {v[4], v[5], v[6], v[7]};
        *(float4*)o       = v0;
        *(float4*)(o + 4) = v1;
    }
}

// ---------------------------------------------------------------------------
extern "C" void kernel_launch(void* const* d_in, const int* in_sizes, int n_in,
                              void* d_out, int out_size) {
    const float* h    = (const float*)d_in[0];
    const float* W    = (const float*)d_in[1];
    const float* a    = (const float*)d_in[2];
    const float* bias = (const float*)d_in[3];
    const void*  adj  = d_in[4];
    float* out = (float*)d_out;

    k_detect<<<1, 256>>>((const unsigned int*)adj);
    k_gemm1<<<(B * L) / 128, 256>>>(h, W, a);

    const int smem = (64 * 128 + 64 * PT_LD + 128) * (int)sizeof(float);
    cudaFuncSetAttribute(k_attn, cudaFuncAttributeMaxDynamicSharedMemorySize, smem);
    dim3 grid(L / 128, B);
    k_attn<<<grid, 256, smem>>>(bias, adj, out);
}